// round 4
// baseline (speedup 1.0000x reference)
#include <cuda_runtime.h>
#include <math.h>
#include <stdint.h>

// Problem constants
#define B_  4096
#define S_  23
#define D_  768
#define H_  8
#define HD_ 96
#define L_  50
#define C_  184      // H_*S_ score columns
#define CP_ 192      // padded score columns
#define UD_ 6912     // 9*D_ : [cls_sum | u_0..u_7]

// ---------------- scratch (device globals; 16B-aligned for float4 access) ----
__device__ __align__(16) float g_qmiss[S_ * D_];
__device__ __align__(16) float g_P[CP_ * D_];
__device__ __align__(16) float g_qb[C_];
__device__ __align__(16) float g_Wcp[L_ * D_];
__device__ __align__(16) float g_Wbig[(size_t)L_ * UD_];
__device__ __align__(16) float g_cbias[L_ + 2];
__device__ __align__(16) float g_logit_mt[L_ + 2];
__device__ __align__(16) float g_mtsum[D_];
__device__ __align__(16) int   g_nexist[B_];
__device__ __align__(16) int   g_start[B_ + 4];
__device__ __align__(16) int   g_rowidx[B_ * S_];
__device__ __align__(16) float g_Y[(size_t)B_ * S_ * CP_];
__device__ __align__(16) float g_U[(size_t)B_ * UD_];

// ---------------- precompute kernels ----------------------------------------

// qmiss[q,:] = missing_table[q,:] @ Wq^T + bq
__global__ void k_qmiss(const float* __restrict__ mt, const float* __restrict__ ipw,
                        const float* __restrict__ ipb) {
    __shared__ float row[D_];
    int q = blockIdx.x;
    for (int i = threadIdx.x; i < D_; i += blockDim.x) row[i] = mt[q * D_ + i];
    __syncthreads();
    for (int o = threadIdx.x; o < D_; o += blockDim.x) {
        const float* w = ipw + (size_t)o * D_;
        float acc = ipb[o];
        #pragma unroll 4
        for (int d = 0; d < D_; d++) acc += row[d] * w[d];
        g_qmiss[q * D_ + o] = acc;
    }
}

// P[c=h*S+q, d] = sum_j qmiss[q, h*96+j] * Wk[h*96+j, d];  qb[c] = qmiss_h . bk_h
__global__ void k_P(const float* __restrict__ ipw, const float* __restrict__ ipb) {
    int c = blockIdx.y;
    int h = c / S_, q = c % S_;
    __shared__ float qr[HD_];
    if (threadIdx.x < HD_) qr[threadIdx.x] = g_qmiss[q * D_ + h * HD_ + threadIdx.x];
    __syncthreads();
    int d = blockIdx.x * blockDim.x + threadIdx.x;
    const float* wk = ipw + (size_t)D_ * D_;
    float acc = 0.f;
    #pragma unroll 8
    for (int j = 0; j < HD_; j++) acc += qr[j] * wk[(size_t)(h * HD_ + j) * D_ + d];
    g_P[(size_t)c * D_ + d] = acc;
    if (blockIdx.x == 0 && threadIdx.x == 0) {
        const float* bk = ipb + D_;
        float s = 0.f;
        for (int j = 0; j < HD_; j++) s += qr[j] * bk[h * HD_ + j];
        g_qb[c] = s;
    }
}

// zero the padding rows of P so vector loads read defined data
__global__ void k_Ppad() {
    int i = blockIdx.x * blockDim.x + threadIdx.x;
    if (i < (CP_ - C_) * D_) g_P[(size_t)C_ * D_ + i] = 0.f;
}

// Wcp[l,:] = pred_w[l,:] @ out_proj_w
__global__ void k_wcp(const float* __restrict__ predw, const float* __restrict__ outw) {
    int l = blockIdx.y;
    __shared__ float pr[D_];
    for (int i = threadIdx.x; i < D_; i += blockDim.x) pr[i] = predw[l * D_ + i];
    __syncthreads();
    int d = blockIdx.x * blockDim.x + threadIdx.x;
    float acc = 0.f;
    #pragma unroll 4
    for (int m = 0; m < D_; m++) acc += pr[m] * outw[(size_t)m * D_ + d];
    g_Wcp[l * D_ + d] = acc;
}

// Wbig[l, 0:768] = pred_w[l,:]/S ; Wbig[l, 768+h*768+d] = (sum_j Wcp[l,h96+j]*Wv[h96+j,d])/S
__global__ void k_wbig(const float* __restrict__ predw, const float* __restrict__ ipw) {
    int l = blockIdx.y;
    __shared__ float wc[D_];
    for (int i = threadIdx.x; i < D_; i += blockDim.x) wc[i] = g_Wcp[l * D_ + i];
    __syncthreads();
    int col = blockIdx.x * blockDim.x + threadIdx.x;
    const float inv = 1.f / (float)S_;
    float v;
    if (col < D_) {
        v = predw[l * D_ + col];
    } else {
        int h = (col - D_) / D_, d = (col - D_) % D_;
        const float* wv = ipw + (size_t)2 * D_ * D_;
        float acc = 0.f;
        #pragma unroll 8
        for (int j = 0; j < HD_; j++) acc += wc[h * HD_ + j] * wv[(size_t)(h * HD_ + j) * D_ + d];
        v = acc;
    }
    g_Wbig[(size_t)l * UD_ + col] = v * inv;
}

__global__ void k_mtsum(const float* __restrict__ mt) {
    int d = threadIdx.x;
    float s = 0.f;
    for (int q = 0; q < S_; q++) s += mt[q * D_ + d];
    g_mtsum[d] = s;
}

// cbias[l] = (bv.Wcp[l] + b_out.pred_w[l]) / S ; logit_mt[l] = mt_sum.pred_w[l]/S + pred_b[l]
__global__ void k_lvec(const float* __restrict__ predw, const float* __restrict__ predb,
                       const float* __restrict__ ipb, const float* __restrict__ outb) {
    int l = threadIdx.x;
    if (l >= L_) return;
    const float inv = 1.f / (float)S_;
    const float* bv = ipb + 2 * D_;
    float cb = 0.f;
    for (int i = 0; i < D_; i++) cb += bv[i] * g_Wcp[l * D_ + i];
    for (int m = 0; m < D_; m++) cb += outb[m] * predw[l * D_ + m];
    g_cbias[l] = cb * inv;
    float lm = 0.f;
    for (int d = 0; d < D_; d++) lm += g_mtsum[d] * predw[l * D_ + d];
    g_logit_mt[l] = lm * inv + predb[l];
}

// ---------------- compaction -------------------------------------------------

__global__ void k_count(const int* __restrict__ ex) {
    int b = blockIdx.x * blockDim.x + threadIdx.x;
    if (b >= B_) return;
    int n = 0;
    for (int s = 0; s < S_; s++) n += (ex[b * S_ + s] != 0);
    g_nexist[b] = n;
}

__global__ void k_scan() {   // single block of 1024 threads, 4 values each
    __shared__ int sm[1024];
    int tid = threadIdx.x;
    int v[4];
    int loc = 0;
    #pragma unroll
    for (int i = 0; i < 4; i++) { v[i] = g_nexist[tid * 4 + i]; loc += v[i]; }
    sm[tid] = loc;
    __syncthreads();
    for (int off = 1; off < 1024; off <<= 1) {
        int add = (tid >= off) ? sm[tid - off] : 0;
        __syncthreads();
        sm[tid] += add;
        __syncthreads();
    }
    int run = sm[tid] - loc;   // exclusive prefix
    #pragma unroll
    for (int i = 0; i < 4; i++) { g_start[tid * 4 + i] = run; run += v[i]; }
    if (tid == 1023) g_start[B_] = run;
}

__global__ void k_rowidx(const int* __restrict__ ex) {
    int b = blockIdx.x * blockDim.x + threadIdx.x;
    if (b >= B_) return;
    int p = g_start[b];
    for (int s = 0; s < S_; s++)
        if (ex[b * S_ + s] != 0) g_rowidx[p++] = b * S_ + s;
}

// ---------------- main scores GEMM: Y[r,c] = cls[rowidx[r],:] . P[c,:] -------
// BM=128, BN=96, BK=16, 256 threads, 8x6 per thread.
// `cls` loads are scalar (no 16B alignment guarantee on harness pointers) and
// use a CLAMPED index so no out-of-range address is ever formed.
__global__ void __launch_bounds__(256) k_gemm(const float* __restrict__ cls) {
    const int total = g_start[B_];
    const int m0 = blockIdx.y * 128;
    if (m0 >= total) return;
    const int n0 = blockIdx.x * 96;
    __shared__ __align__(16) float As[16][128];
    __shared__ __align__(16) float Bs[16][96];
    __shared__ int rsrc[128];
    int tid = threadIdx.x;
    if (tid < 128) {
        int r = m0 + tid;
        rsrc[tid] = (r < total) ? g_rowidx[r] : -1;
    }
    __syncthreads();
    float acc[8][6];
    #pragma unroll
    for (int i = 0; i < 8; i++)
        #pragma unroll
        for (int j = 0; j < 6; j++) acc[i][j] = 0.f;
    int ty = tid >> 4, tx = tid & 15;
    for (int k0 = 0; k0 < D_; k0 += 16) {
        #pragma unroll
        for (int i = 0; i < 2; i++) {
            int idx = i * 256 + tid;
            int row = idx >> 2, c0 = (idx & 3) * 4;
            int src = rsrc[row];
            int srcc = (src >= 0) ? src : 0;              // clamp: always in-bounds
            const float* sp = cls + (size_t)srcc * D_ + k0 + c0;
            #pragma unroll
            for (int j = 0; j < 4; j++) {
                float v = sp[j];                          // scalar LDG.32, in-bounds
                As[c0 + j][row] = (src >= 0) ? v : 0.f;
            }
        }
        #pragma unroll
        for (int i = 0; i < 2; i++) {
            int idx = i * 256 + tid;
            if (idx < 384) {
                int row = idx >> 2, c4 = idx & 3;
                float4 v = *(const float4*)(g_P + (size_t)(n0 + row) * D_ + k0 + c4 * 4);
                Bs[c4 * 4 + 0][row] = v.x; Bs[c4 * 4 + 1][row] = v.y;
                Bs[c4 * 4 + 2][row] = v.z; Bs[c4 * 4 + 3][row] = v.w;
            }
        }
        __syncthreads();
        #pragma unroll
        for (int k = 0; k < 16; k++) {
            float a[8], bb[6];
            #pragma unroll
            for (int i = 0; i < 8; i++) a[i] = As[k][ty * 8 + i];
            #pragma unroll
            for (int j = 0; j < 6; j++) bb[j] = Bs[k][tx * 6 + j];
            #pragma unroll
            for (int i = 0; i < 8; i++)
                #pragma unroll
                for (int j = 0; j < 6; j++) acc[i][j] += a[i] * bb[j];
        }
        __syncthreads();
    }
    #pragma unroll
    for (int i = 0; i < 8; i++) {
        int r = m0 + ty * 8 + i;
        if (r < total) {
            float* yp = g_Y + (size_t)r * CP_ + n0 + tx * 6;
            #pragma unroll
            for (int j = 0; j < 6; j++) yp[j] = acc[i][j];
        }
    }
}

// ---------------- per-sample attention + reduction ---------------------------
__global__ void __launch_bounds__(128) k_attn(const float* __restrict__ cls,
                                              const int* __restrict__ ex) {
    int b = blockIdx.x;
    int tid = threadIdx.x;
    __shared__ float Ys[S_][C_];
    __shared__ float shk[H_][S_];
    __shared__ float qbs[C_];
    __shared__ int ke[S_], qm[S_];
    __shared__ int info[3];
    if (tid == 0) {
        int ne = 0, nm = 0;
        for (int s = 0; s < S_; s++) {
            if (ex[b * S_ + s] != 0) ke[ne++] = s; else qm[nm++] = s;
        }
        info[0] = ne; info[1] = nm; info[2] = g_start[b];
    }
    for (int i = tid; i < C_; i += 128) qbs[i] = g_qb[i];
    for (int i = tid; i < H_ * S_; i += 128) (&shk[0][0])[i] = 0.f;
    __syncthreads();
    int ne = info[0], nm = info[1], st = info[2];
    if (ne == 0) {   // all-missing sample: U row must be deterministic zeros
        for (int i = tid; i < UD_; i += 128) g_U[(size_t)b * UD_ + i] = 0.f;
        return;
    }
    for (int i = tid; i < ne * C_; i += 128) {
        int k = i / C_, c = i % C_;
        Ys[k][c] = g_Y[(size_t)(st + k) * CP_ + c];
    }
    __syncthreads();
    const float scale = rsqrtf((float)HD_);
    // softmax per (head, missing query); accumulate attention weights into s_hk
    for (int p = tid; p < H_ * nm; p += 128) {
        int h = p / nm, qi = p % nm;
        int c = h * S_ + qm[qi];
        float qb = qbs[c];
        float mx = -3.0e38f;
        for (int k = 0; k < ne; k++) mx = fmaxf(mx, scale * (Ys[k][c] + qb));
        float sum = 0.f;
        for (int k = 0; k < ne; k++) sum += expf(scale * (Ys[k][c] + qb) - mx);
        float inv = 1.f / sum;
        for (int k = 0; k < ne; k++) {
            float a = expf(scale * (Ys[k][c] + qb) - mx) * inv;
            atomicAdd(&shk[h][k], a);
        }
    }
    __syncthreads();
    // U[b] = [cls_sum | u_h = sum_k s_hk * cls(existing k)]
    for (int ch = 0; ch < D_ / 128; ch++) {
        int d = ch * 128 + tid;
        float cs = 0.f;
        float au[H_];
        #pragma unroll
        for (int h = 0; h < H_; h++) au[h] = 0.f;
        for (int k = 0; k < ne; k++) {
            float c = cls[((size_t)b * S_ + ke[k]) * D_ + d];   // scalar load
            cs += c;
            #pragma unroll
            for (int h = 0; h < H_; h++) au[h] += shk[h][k] * c;
        }
        size_t ub = (size_t)b * UD_;
        g_U[ub + d] = cs;
        #pragma unroll
        for (int h = 0; h < H_; h++) g_U[ub + D_ + (size_t)h * D_ + d] = au[h];
    }
}

// ---------------- final logits GEMM + epilogue --------------------------------
__global__ void k_zero(float* out) {
    int i = blockIdx.x * blockDim.x + threadIdx.x;
    if (i < B_ * L_) out[i] = 0.f;
}

#define KSPLIT 8
#define KSLICE (UD_ / KSPLIT)   // 864
// logits += U[64 rows] @ Wbig^T over a K slice (split-K with atomic add)
// Bs padded to 64 columns: thread tx reads Bs[k][tx*4 .. tx*4+3], tx up to 15
// -> column 63. (The 56-wide version read out of bounds -> illegal access.)
__global__ void __launch_bounds__(256) k_final(float* __restrict__ out) {
    int m0 = blockIdx.x * 64;
    int koff0 = blockIdx.y * KSLICE;
    __shared__ __align__(16) float As[16][64];
    __shared__ __align__(16) float Bs[16][64];
    int tid = threadIdx.x;
    int ty = tid >> 4, tx = tid & 15;
    float acc[4][4];
    #pragma unroll
    for (int i = 0; i < 4; i++)
        #pragma unroll
        for (int j = 0; j < 4; j++) acc[i][j] = 0.f;
    for (int k0 = 0; k0 < KSLICE; k0 += 16) {
        int kb = koff0 + k0;
        #pragma unroll
        for (int i = 0; i < 4; i++) {
            int id = i * 256 + tid;
            int m = id >> 4, k = id & 15;
            As[k][m] = g_U[(size_t)(m0 + m) * UD_ + kb + k];
        }
        #pragma unroll
        for (int i = 0; i < 4; i++) {
            int id = i * 256 + tid;
            int k = id >> 6, n = id & 63;
            Bs[k][n] = (n < L_) ? g_Wbig[(size_t)n * UD_ + kb + k] : 0.f;
        }
        __syncthreads();
        #pragma unroll
        for (int k = 0; k < 16; k++) {
            float4 a4 = *(const float4*)&As[k][ty * 4];
            float4 b4 = *(const float4*)&Bs[k][tx * 4];
            float a[4] = {a4.x, a4.y, a4.z, a4.w};
            float bb[4] = {b4.x, b4.y, b4.z, b4.w};
            #pragma unroll
            for (int i = 0; i < 4; i++)
                #pragma unroll
                for (int j = 0; j < 4; j++) acc[i][j] += a[i] * bb[j];
        }
        __syncthreads();
    }
    #pragma unroll
    for (int i = 0; i < 4; i++) {
        int m = m0 + ty * 4 + i;
        #pragma unroll
        for (int j = 0; j < 4; j++) {
            int n = tx * 4 + j;
            if (n < L_) atomicAdd(&out[(size_t)m * L_ + n], acc[i][j]);
        }
    }
}

__global__ void k_epi(float* __restrict__ out, const float* __restrict__ predb) {
    int b = blockIdx.x;
    int l = threadIdx.x;
    if (l >= L_) return;
    int ne = g_nexist[b];
    if (ne == 0) out[(size_t)b * L_ + l] = g_logit_mt[l];
    else out[(size_t)b * L_ + l] += (float)(S_ - ne) * g_cbias[l] + predb[l];
}

// ---------------- launch ------------------------------------------------------
extern "C" void kernel_launch(void* const* d_in, const int* in_sizes, int n_in,
                              void* d_out, int out_size) {
    // Identify inputs by unique element counts (robust to ordering), with a
    // positional fallback if anything fails to match.
    const float *cls = 0, *mt = 0, *ipw = 0, *ipb = 0, *outw = 0, *outb = 0,
                *predw = 0, *predb = 0;
    const int* ex = 0;
    for (int i = 0; i < n_in; i++) {
        switch (in_sizes[i]) {
            case B_ * S_ * D_:  cls   = (const float*)d_in[i]; break;  // 72351744
            case S_ * D_:       mt    = (const float*)d_in[i]; break;  // 17664
            case 3 * D_ * D_:   ipw   = (const float*)d_in[i]; break;  // 1769472
            case 3 * D_:        ipb   = (const float*)d_in[i]; break;  // 2304
            case D_ * D_:       outw  = (const float*)d_in[i]; break;  // 589824
            case D_:            outb  = (const float*)d_in[i]; break;  // 768
            case L_ * D_:       predw = (const float*)d_in[i]; break;  // 38400
            case L_:            predb = (const float*)d_in[i]; break;  // 50
            case B_ * S_:       ex    = (const int*)d_in[i];   break;  // 94208
        }
    }
    if (!cls || !mt || !ipw || !ipb || !outw || !outb || !predw || !predb || !ex) {
        cls   = (const float*)d_in[0];
        mt    = (const float*)d_in[1];
        ipw   = (const float*)d_in[2];
        ipb   = (const float*)d_in[3];
        outw  = (const float*)d_in[4];
        outb  = (const float*)d_in[5];
        predw = (const float*)d_in[6];
        predb = (const float*)d_in[7];
        ex    = (const int*)d_in[8];
    }
    float* out = (float*)d_out;

    // precompute folded weights
    k_qmiss<<<S_, 256>>>(mt, ipw, ipb);
    k_P<<<dim3(3, C_), 256>>>(ipw, ipb);
    k_Ppad<<<((CP_ - C_) * D_ + 255) / 256, 256>>>();
    k_wcp<<<dim3(3, L_), 256>>>(predw, outw);
    k_wbig<<<dim3(27, L_), 256>>>(predw, ipw);
    k_mtsum<<<1, D_>>>(mt);
    k_lvec<<<1, 64>>>(predw, predb, ipb, outb);

    // compaction of existing (b,s) rows
    k_count<<<B_ / 256, 256>>>(ex);
    k_scan<<<1, 1024>>>();
    k_rowidx<<<B_ / 256, 256>>>(ex);

    // main pipeline
    k_gemm<<<dim3(2, (B_ * S_) / 128), 256>>>(cls);
    k_attn<<<B_, 128>>>(cls, ex);
    k_zero<<<(B_ * L_ + 255) / 256, 256>>>(out);
    k_final<<<dim3(B_ / 64, KSPLIT), 256>>>(out);
    k_epi<<<B_, 64>>>(out, predb);
}